// round 16
// baseline (speedup 1.0000x reference)
#include <cuda_runtime.h>
#include <math.h>

#define NN 50000

// ---------------- scratch (static device globals; referenced directly in kernels) ----
__device__ float g_W1f[384 * 512];             // [W1l | W1r] fused
__device__ float g_W2f[256 * 256];             // [W2l | W2r] fused
__device__ float g_y1[(size_t)NN * 512];       // [xcat@W1l | xcat@W1r]
__device__ float g_agg1[(size_t)NN * 256];     // edge-agg of y1l
__device__ float g_cnt[NN];                    // in-degree
__device__ float g_h1[(size_t)NN * 256];       // relu SAGE1 out
__device__ float g_y2[(size_t)NN * 256];       // [h1@W2l | h1@W2r]
__device__ float g_agg2[(size_t)NN * 128];
__device__ float g_hg[(size_t)NN * 128];       // normalized h_g
__device__ float g_hidden[(size_t)NN * 256];   // classifier hidden
__device__ int   g_idx64;                      // 1 if edge_index is int64-layout

// ---------------- index dtype detection ----------------
// If edge_index is int64 (values < 2^31, nonneg), every odd 32-bit word is 0.
// If it was downcast to int32, odd words are random node indices (mostly nonzero).
__global__ void k_detect_idx(const int* __restrict__ e, int nPairsToCheck) {
    if (blockIdx.x == 0 && threadIdx.x == 0) {
        int is64 = 1;
        for (int i = 0; i < nPairsToCheck; i++) {
            if (e[2 * i + 1] != 0) { is64 = 0; break; }
        }
        g_idx64 = is64;
    }
}

// ---------------- utility kernels ----------------
__global__ void k_zero_scratch(int n) {
    size_t n0 = (size_t)n * 256;     // agg1
    size_t n1 = (size_t)n * 128;     // agg2
    size_t n2 = (size_t)n;           // cnt
    size_t total = n0 + n1 + n2;
    size_t i = (size_t)blockIdx.x * blockDim.x + threadIdx.x;
    size_t stride = (size_t)gridDim.x * blockDim.x;
    for (; i < total; i += stride) {
        if (i < n0) g_agg1[i] = 0.f;
        else if (i < n0 + n1) g_agg2[i - n0] = 0.f;
        else g_cnt[i - n0 - n1] = 0.f;
    }
}

__global__ void k_fuseW1(const float* __restrict__ Wl, const float* __restrict__ Wr) {
    int i = blockIdx.x * blockDim.x + threadIdx.x;
    int total = 384 * 256;
    int stride = gridDim.x * blockDim.x;
    for (; i < total; i += stride) {
        int k = i >> 8, j = i & 255;
        g_W1f[(size_t)k * 512 + j] = Wl[i];
        g_W1f[(size_t)k * 512 + 256 + j] = Wr[i];
    }
}

__global__ void k_fuseW2(const float* __restrict__ Wl, const float* __restrict__ Wr) {
    int i = blockIdx.x * blockDim.x + threadIdx.x;
    int total = 256 * 128;
    int stride = gridDim.x * blockDim.x;
    for (; i < total; i += stride) {
        int k = i >> 7, j = i & 127;
        g_W2f[(size_t)k * 256 + j] = Wl[i];
        g_W2f[(size_t)k * 256 + 128 + j] = Wr[i];
    }
}

// ---------------- SGEMM body: C[M,Nc] = A[M,K] @ B[K,Nc] (+bias)(+relu) --------
// 128x128 block tile, BK=16, 256 threads, 8x8 per thread, double-buffered smem.
template <bool RELU, int NSEG>
__device__ __forceinline__ void sgemm_body(
        const float* __restrict__ A0, const float* __restrict__ A1,
        const float* __restrict__ A2, const float* __restrict__ A3, int lda,
        const float* __restrict__ B,
        const float* __restrict__ bias,
        float* __restrict__ C, int ldc, int colOff,
        int M, int K, int Nc, int tileX, int tileY) {
    __shared__ float As[2][16][128];   // [buf][k][m]
    __shared__ float Bs[2][16][128];   // [buf][k][n]
    const int tid = threadIdx.x;
    const int tx = tid & 15;
    const int ty = tid >> 4;
    const int rowBase = tileY * 128;
    const int colBase = tileX * 128;

    const int aRow = tid >> 1;
    const int aCol = (tid & 1) * 8;
    const int aGrRaw = rowBase + aRow;
    const bool aOk = (aGrRaw < M);
    const int aGr = aOk ? aGrRaw : 0;

    const int bRow = tid >> 4;
    const int bCol = (tid & 15) * 8;
    const float* bPtr = B + (size_t)bRow * Nc + colBase + bCol;

    float acc[8][8];
#pragma unroll
    for (int i = 0; i < 8; i++)
#pragma unroll
        for (int j = 0; j < 8; j++) acc[i][j] = 0.f;

    float4 pa0, pa1, pb0, pb1;

    auto loadA = [&](int kk, float4& v0, float4& v1) {
        const float* ap;
        if (NSEG > 1) {
            int col = kk + aCol;
            int seg = col >> 7;
            int off = col & 127;
            const float* base = A0;
            if (NSEG >= 2 && seg == 1) base = A1;
            if (NSEG >= 3 && seg == 2) base = A2;
            if (NSEG >= 4 && seg == 3) base = A3;
            ap = base + (size_t)aGr * 128 + off;
        } else {
            ap = A0 + (size_t)aGr * lda + kk + aCol;
        }
        if (aOk) {
            v0 = *reinterpret_cast<const float4*>(ap);
            v1 = *reinterpret_cast<const float4*>(ap + 4);
        } else {
            v0 = make_float4(0.f, 0.f, 0.f, 0.f);
            v1 = v0;
        }
    };

    loadA(0, pa0, pa1);
    pb0 = *reinterpret_cast<const float4*>(bPtr);
    pb1 = *reinterpret_cast<const float4*>(bPtr + 4);

    int buf = 0;
    As[buf][aCol + 0][aRow] = pa0.x;
    As[buf][aCol + 1][aRow] = pa0.y;
    As[buf][aCol + 2][aRow] = pa0.z;
    As[buf][aCol + 3][aRow] = pa0.w;
    As[buf][aCol + 4][aRow] = pa1.x;
    As[buf][aCol + 5][aRow] = pa1.y;
    As[buf][aCol + 6][aRow] = pa1.z;
    As[buf][aCol + 7][aRow] = pa1.w;
    *reinterpret_cast<float4*>(&Bs[buf][bRow][bCol]) = pb0;
    *reinterpret_cast<float4*>(&Bs[buf][bRow][bCol + 4]) = pb1;
    __syncthreads();

    for (int kk = 0; kk < K; kk += 16) {
        const bool hasNext = (kk + 16) < K;
        if (hasNext) {
            loadA(kk + 16, pa0, pa1);
            const float* bp = bPtr + (size_t)(kk + 16) * Nc;
            pb0 = *reinterpret_cast<const float4*>(bp);
            pb1 = *reinterpret_cast<const float4*>(bp + 4);
        }
#pragma unroll
        for (int k = 0; k < 16; k++) {
            float4 a0 = *reinterpret_cast<const float4*>(&As[buf][k][ty * 8]);
            float4 a1 = *reinterpret_cast<const float4*>(&As[buf][k][ty * 8 + 4]);
            float4 b0 = *reinterpret_cast<const float4*>(&Bs[buf][k][tx * 8]);
            float4 b1 = *reinterpret_cast<const float4*>(&Bs[buf][k][tx * 8 + 4]);
            float ar[8] = {a0.x, a0.y, a0.z, a0.w, a1.x, a1.y, a1.z, a1.w};
            float br[8] = {b0.x, b0.y, b0.z, b0.w, b1.x, b1.y, b1.z, b1.w};
#pragma unroll
            for (int i = 0; i < 8; i++)
#pragma unroll
                for (int j = 0; j < 8; j++)
                    acc[i][j] = fmaf(ar[i], br[j], acc[i][j]);
        }
        if (hasNext) {
            int nb = buf ^ 1;
            As[nb][aCol + 0][aRow] = pa0.x;
            As[nb][aCol + 1][aRow] = pa0.y;
            As[nb][aCol + 2][aRow] = pa0.z;
            As[nb][aCol + 3][aRow] = pa0.w;
            As[nb][aCol + 4][aRow] = pa1.x;
            As[nb][aCol + 5][aRow] = pa1.y;
            As[nb][aCol + 6][aRow] = pa1.z;
            As[nb][aCol + 7][aRow] = pa1.w;
            *reinterpret_cast<float4*>(&Bs[nb][bRow][bCol]) = pb0;
            *reinterpret_cast<float4*>(&Bs[nb][bRow][bCol + 4]) = pb1;
            __syncthreads();
            buf = nb;
        }
    }

    const int c0 = colBase + tx * 8;
    float4 bb0 = make_float4(0.f, 0.f, 0.f, 0.f);
    float4 bb1 = bb0;
    if (bias) {
        bb0 = *reinterpret_cast<const float4*>(bias + c0);
        bb1 = *reinterpret_cast<const float4*>(bias + c0 + 4);
    }
#pragma unroll
    for (int i = 0; i < 8; i++) {
        int r = rowBase + ty * 8 + i;
        if (r < M) {
            float4 v0, v1;
            v0.x = acc[i][0] + bb0.x; v0.y = acc[i][1] + bb0.y;
            v0.z = acc[i][2] + bb0.z; v0.w = acc[i][3] + bb0.w;
            v1.x = acc[i][4] + bb1.x; v1.y = acc[i][5] + bb1.y;
            v1.z = acc[i][6] + bb1.z; v1.w = acc[i][7] + bb1.w;
            if (RELU) {
                v0.x = fmaxf(v0.x, 0.f); v0.y = fmaxf(v0.y, 0.f);
                v0.z = fmaxf(v0.z, 0.f); v0.w = fmaxf(v0.w, 0.f);
                v1.x = fmaxf(v1.x, 0.f); v1.y = fmaxf(v1.y, 0.f);
                v1.z = fmaxf(v1.z, 0.f); v1.w = fmaxf(v1.w, 0.f);
            }
            float* cp = C + (size_t)r * ldc + colOff + c0;
            *reinterpret_cast<float4*>(cp) = v0;
            *reinterpret_cast<float4*>(cp + 4) = v1;
        }
    }
}

// layer 1: [h_v|h_t|h_tab] @ g_W1f -> g_y1 [N,512]
__global__ void __launch_bounds__(256)
k_l1gemm(const float* __restrict__ h_v, const float* __restrict__ h_t,
         const float* __restrict__ h_tab, int M) {
    sgemm_body<false, 3>(h_v, h_t, h_tab, nullptr, 0, g_W1f, nullptr,
                         g_y1, 512, 0, M, 384, 512, blockIdx.x, blockIdx.y);
}

// layer 2: g_h1 @ g_W2f -> g_y2 [N,256]
__global__ void __launch_bounds__(256)
k_l2gemm(int M) {
    sgemm_body<false, 1>(g_h1, nullptr, nullptr, nullptr, 256, g_W2f, nullptr,
                         g_y2, 256, 0, M, 256, 256, blockIdx.x, blockIdx.y);
}

// projections: z selects (A, B, bias); writes contiguous z regions of d_out.
__global__ void __launch_bounds__(256)
k_proj3(const float* __restrict__ Aht, const float* __restrict__ Ahtab,
        const float* __restrict__ Wsh, const float* __restrict__ bsh,
        const float* __restrict__ Wst, const float* __restrict__ bst,
        const float* __restrict__ Wstab, const float* __restrict__ bstab,
        float* __restrict__ zout, int M) {
    const float* A;
    const float* B;
    const float* bias;
    int z = blockIdx.z;
    if (z == 0)      { A = g_hg;  B = Wsh;   bias = bsh;   }
    else if (z == 1) { A = Aht;   B = Wst;   bias = bst;   }
    else             { A = Ahtab; B = Wstab; bias = bstab; }
    float* C = zout + (size_t)z * M * 128;
    sgemm_body<false, 1>(A, nullptr, nullptr, nullptr, 128, B, bias,
                         C, 128, 0, M, 128, 128, blockIdx.x, blockIdx.y);
}

// classifier: [z_shared|z_t|z_tab|g_hg] @ Wc1 + bc1, relu -> g_hidden [N,256]
__global__ void __launch_bounds__(256)
k_clsgemm(const float* __restrict__ zout,
          const float* __restrict__ Wc1, const float* __restrict__ bc1, int M) {
    sgemm_body<true, 4>(zout, zout + (size_t)M * 128, zout + (size_t)M * 256,
                        g_hg, 0, Wc1, bc1, g_hidden, 256, 0,
                        M, 512, 256, blockIdx.x, blockIdx.y);
}

// ---------------- edge kernels ----------------
// warp per edge. Index layout chosen at runtime via g_idx64 (int32 vs int64).
// LAYER1: X=g_y1 (ld 512, cols 0:256) -> g_agg1, + degree count.
// else:   X=g_y2 (ld 256, cols 0:128) -> g_agg2.
template <bool LAYER1>
__global__ void k_edge_agg(const void* __restrict__ eidx, int E, int N) {
    const int is64 = g_idx64;
    int gwarp = (blockIdx.x * blockDim.x + threadIdx.x) >> 5;
    int lane = threadIdx.x & 31;
    int nWarps = (gridDim.x * blockDim.x) >> 5;
    const long long* e64 = (const long long*)eidx;
    const int* e32 = (const int*)eidx;
    for (int e = gwarp; e < E; e += nWarps) {
        int s, d;
        if (is64) {
            s = (int)e64[e];
            d = (int)e64[E + e];
        } else {
            s = e32[e];
            d = e32[E + e];
        }
        // bounds guard: wrong layout guess -> skip (diagnosable via rel_err) not trap
        if ((unsigned)s >= (unsigned)N || (unsigned)d >= (unsigned)N) continue;
        if (LAYER1) {
            if (lane == 0) atomicAdd(&g_cnt[d], 1.0f);
            const float4* xs = reinterpret_cast<const float4*>(&g_y1[(size_t)s * 512]);
            float* ad = &g_agg1[(size_t)d * 256];
#pragma unroll
            for (int p = lane; p < 64; p += 32) {
                float4 v = xs[p];
                atomicAdd(ad + p * 4 + 0, v.x);
                atomicAdd(ad + p * 4 + 1, v.y);
                atomicAdd(ad + p * 4 + 2, v.z);
                atomicAdd(ad + p * 4 + 3, v.w);
            }
        } else {
            const float4* xs = reinterpret_cast<const float4*>(&g_y2[(size_t)s * 256]);
            float* ad = &g_agg2[(size_t)d * 128];
            float4 v = xs[lane];
            atomicAdd(ad + lane * 4 + 0, v.x);
            atomicAdd(ad + lane * 4 + 1, v.y);
            atomicAdd(ad + lane * 4 + 2, v.z);
            atomicAdd(ad + lane * 4 + 3, v.w);
        }
    }
}

// g_h1 = relu(g_agg1/max(cnt,1) + b1g + g_y1[:,256:512])
__global__ void k_combine1(const float* __restrict__ b1g, int n) {
    size_t idx = (size_t)blockIdx.x * blockDim.x + threadIdx.x;
    size_t total = (size_t)n * 64;
    size_t stride = (size_t)gridDim.x * blockDim.x;
    for (; idx < total; idx += stride) {
        int row = (int)(idx >> 6);
        int j4 = (int)(idx & 63);
        float inv = 1.0f / fmaxf(g_cnt[row], 1.0f);
        float4 a = reinterpret_cast<const float4*>(g_agg1)[idx];
        float4 y = reinterpret_cast<const float4*>(g_y1)[(size_t)row * 128 + 64 + j4];
        float4 b = reinterpret_cast<const float4*>(b1g)[j4];
        float4 o;
        o.x = fmaxf(a.x * inv + b.x + y.x, 0.f);
        o.y = fmaxf(a.y * inv + b.y + y.y, 0.f);
        o.z = fmaxf(a.z * inv + b.z + y.z, 0.f);
        o.w = fmaxf(a.w * inv + b.w + y.w, 0.f);
        reinterpret_cast<float4*>(g_h1)[idx] = o;
    }
}

// g_hg row = normalize(g_agg2/max(cnt,1) + b2g + g_y2[:,128:256]); warp per row
__global__ void k_combine2_norm(const float* __restrict__ b2g, int n) {
    int warpId = (blockIdx.x * blockDim.x + threadIdx.x) >> 5;
    int lane = threadIdx.x & 31;
    if (warpId >= n) return;
    int row = warpId;
    float inv = 1.0f / fmaxf(g_cnt[row], 1.0f);
    float v[4];
    float s = 0.f;
#pragma unroll
    for (int q = 0; q < 4; q++) {
        int c = lane + q * 32;
        v[q] = g_agg2[(size_t)row * 128 + c] * inv + b2g[c]
             + g_y2[(size_t)row * 256 + 128 + c];
        s = fmaf(v[q], v[q], s);
    }
#pragma unroll
    for (int o = 16; o > 0; o >>= 1) s += __shfl_xor_sync(0xffffffffu, s, o);
    float scale = 1.0f / fmaxf(sqrtf(s), 1e-12f);
#pragma unroll
    for (int q = 0; q < 4; q++) {
        g_hg[(size_t)row * 128 + lane + q * 32] = v[q] * scale;
    }
}

// logits = g_hidden @ Wc2 + bc2   (K=256, Nc=14), 8 rows per block of 128 threads
__global__ void k_logits(const float* __restrict__ Wc2, const float* __restrict__ bc2,
                         float* __restrict__ out, int n) {
    __shared__ float Ws[256 * 14];
    __shared__ float Hs[8][256];
    int tid = threadIdx.x;
    for (int i = tid; i < 256 * 14; i += 128) Ws[i] = Wc2[i];
    int rowBase = blockIdx.x * 8;
    for (int i = tid; i < 8 * 256; i += 128) {
        int r = i >> 8;
        int k = i & 255;
        int gr = rowBase + r;
        Hs[r][k] = (gr < n) ? g_hidden[(size_t)gr * 256 + k] : 0.f;
    }
    __syncthreads();
    if (tid < 112) {
        int r = tid / 14;
        int c = tid % 14;
        int gr = rowBase + r;
        if (gr < n) {
            float sum = 0.f;
#pragma unroll 8
            for (int k = 0; k < 256; k++) sum = fmaf(Hs[r][k], Ws[k * 14 + c], sum);
            out[(size_t)gr * 14 + c] = sum + bc2[c];
        }
    }
}

// ---------------- launch ----------------
extern "C" void kernel_launch(void* const* d_in, const int* in_sizes, int n_in,
                              void* d_out, int out_size) {
    const float* h_v   = (const float*)d_in[0];
    const float* h_t   = (const float*)d_in[1];
    const float* h_tab = (const float*)d_in[2];
    const void*  eidx  = d_in[3];
    const float* W1l = (const float*)d_in[4];
    const float* W1r = (const float*)d_in[5];
    const float* b1g = (const float*)d_in[6];
    const float* W2l = (const float*)d_in[7];
    const float* W2r = (const float*)d_in[8];
    const float* b2g = (const float*)d_in[9];
    const float* Wsh = (const float*)d_in[10];
    const float* bsh = (const float*)d_in[11];
    const float* Wst = (const float*)d_in[12];
    const float* bst = (const float*)d_in[13];
    const float* Wstab = (const float*)d_in[14];
    const float* bstab = (const float*)d_in[15];
    const float* Wc1 = (const float*)d_in[16];
    const float* bc1 = (const float*)d_in[17];
    const float* Wc2 = (const float*)d_in[18];
    const float* bc2 = (const float*)d_in[19];
    float* out = (float*)d_out;

    const int N = in_sizes[0] / 128;
    const int E = in_sizes[3] / 2;

    float* zout = out + (size_t)N * 14;   // z_shared | z_t | z_tab regions

    // detect edge-index layout (reads first 256 pairs' odd words)
    k_detect_idx<<<1, 1>>>((const int*)eidx, 256);

    // zero accumulators + counts
    k_zero_scratch<<<4096, 256>>>(N);

    // fuse weights
    k_fuseW1<<<256, 256>>>(W1l, W1r);
    k_fuseW2<<<128, 256>>>(W2l, W2r);

    dim3 blk(256);
    int mTiles = (N + 127) / 128;

    // layer 1 fused GEMM
    k_l1gemm<<<dim3(4, mTiles), blk>>>(h_v, h_t, h_tab, N);

    // edge aggregation (256-dim) + degree count
    k_edge_agg<true><<<16384, 256>>>(eidx, E, N);

    // SAGE1 combine + relu
    k_combine1<<<4096, 256>>>(b1g, N);

    // layer 2 fused GEMM
    k_l2gemm<<<dim3(2, mTiles), blk>>>(N);

    // edge aggregation (128-dim)
    k_edge_agg<false><<<16384, 256>>>(eidx, E, N);

    // SAGE2 combine + L2-normalize
    k_combine2_norm<<<(N * 32 + 255) / 256, 256>>>(b2g, N);

    // three projections -> d_out z regions
    k_proj3<<<dim3(1, mTiles, 3), blk>>>(h_t, h_tab,
                                         Wsh, bsh, Wst, bst, Wstab, bstab,
                                         zout, N);

    // classifier hidden
    k_clsgemm<<<dim3(2, mTiles), blk>>>(zout, Wc1, bc1, N);

    // logits
    k_logits<<<(N + 7) / 8, 128>>>(Wc2, bc2, out, N);
}